// round 14
// baseline (speedup 1.0000x reference)
#include <cuda_runtime.h>
#include <cuda_bf16.h>
#include <cstdint>

// ---------------- problem constants ----------------
#define Bb    32
#define Tt    128
#define Pp    512
#define MAXL  7
#define Dd    300
#define KSEG  320            // per-segment K (>=300)
#define KP    (3*KSEG)       // 960 = 15*64 ; segments A=[h,h,m], B=[h,m,h]
#define NP    6144           // packed N: 256 patterns x 11 + 256 x 13
#define Mm    4096           // B*T (max)
#define NCc   2
#define NEGV  (-1e30f)

// gemm tiling: CTA 128(M) x 256(N), 8 warps (2M x 4N), warp tile 64x64, BK=64
#define TILE_M 128
#define TILE_N 256
#define BK    64
#define NKT   (KP/BK)        // 15
#define NSTG  3
#define ROWB  144            // 128 B data + 16 pad -> conflict-free ldmatrix
#define STAGE_A   (TILE_M*ROWB)          // 18432
#define STAGE_B   (TILE_N*ROWB)          // 36864
#define STAGE_SZ  (STAGE_A+STAGE_B)      // 55296
#define SMEM_GEMM (NSTG*STAGE_SZ)        // 165888
#define CPT 12   // cp.async 16B tasks/thread/stage

// scan chunking
#define SCH 6    // timesteps per register buffer

// ---------------- scratch ----------------
__device__ __nv_bfloat16 g_Aq[(size_t)Mm * KP];   // [h,h,m], M-compacted
__device__ __nv_bfloat16 g_Bq[(size_t)NP * KP];   // [h,m,h], N-packed
__device__ float g_biasP[NP];                     // packed bias
__device__ float g_ts[(size_t)Mm * NP];           // M-compacted, N-packed
__device__ float g_scores[Bb * Pp];

// ---------------- PTX helpers ----------------
__device__ __forceinline__ void cpasync16(uint32_t s, const void* g){
    asm volatile("cp.async.cg.shared.global [%0], [%1], 16;" :: "r"(s), "l"(g));
}
__device__ __forceinline__ void cp_commit(){
    asm volatile("cp.async.commit_group;" ::: "memory");
}
template<int N> __device__ __forceinline__ void cp_wait(){
    asm volatile("cp.async.wait_group %0;" :: "n"(N) : "memory");
}
__device__ __forceinline__ void ldsm4(uint32_t a, uint32_t& r0, uint32_t& r1, uint32_t& r2, uint32_t& r3){
    asm volatile("ldmatrix.sync.aligned.m8n8.x4.shared.b16 {%0,%1,%2,%3}, [%4];"
                 : "=r"(r0), "=r"(r1), "=r"(r2), "=r"(r3) : "r"(a));
}
__device__ __forceinline__ void mma16816(float* c, uint32_t a0, uint32_t a1, uint32_t a2, uint32_t a3,
                                         uint32_t b0, uint32_t b1){
    asm volatile("mma.sync.aligned.m16n8k16.row.col.f32.bf16.bf16.f32 "
                 "{%0,%1,%2,%3}, {%4,%5,%6,%7}, {%8,%9}, {%0,%1,%2,%3};"
                 : "+f"(c[0]), "+f"(c[1]), "+f"(c[2]), "+f"(c[3])
                 : "r"(a0), "r"(a1), "r"(a2), "r"(a3), "r"(b0), "r"(b1));
}

// ---------------- 1. bf16 split conversion of A ----------------
__global__ void convA_kernel(const int* __restrict__ tokens, const float* __restrict__ emb,
                             const int* __restrict__ doc_lens){
    int b = blockIdx.x >> 7, t = blockIdx.x & 127;
    if (t >= doc_lens[b]) return;
    int off = 0;
    for (int i = 0; i < b; i++) off += doc_lens[i];
    int mrow = off + t;
    int tok = tokens[blockIdx.x];
    __nv_bfloat16* row = g_Aq + (size_t)mrow * KP;
    const float* src = emb + (size_t)tok * Dd;
    for (int k = threadIdx.x; k < KSEG; k += blockDim.x){
        float x = (k < Dd) ? src[k] : 0.0f;
        __nv_bfloat16 h = __float2bfloat16(x);
        __nv_bfloat16 m = __float2bfloat16(x - __bfloat162float(h));
        row[0*KSEG + k] = h;  row[1*KSEG + k] = h;  row[2*KSEG + k] = m;
    }
}

// ---------------- 2. bf16 split conversion of B, packed-N remap ----------------
__global__ void convB_kernel(const float* __restrict__ diags, const float* __restrict__ bias){
    int n = blockIdx.x;
    int p, d, m;
    if (n < 2816){
        p = n / 11; int r = n % 11;
        d = (r < 6) ? 0 : 1; m = d ? (r - 6) : r;
    } else {
        int q = n - 2816;
        p = 256 + q / 13; int r = q % 13;
        d = (r < 7) ? 0 : 1; m = d ? (r - 7) : r;
    }
    int k = p*14 + d*7 + m;
    const float* src = diags + (size_t)k * Dd;
    __nv_bfloat16* row = g_Bq + (size_t)n * KP;
    for (int kk = threadIdx.x; kk < KSEG; kk += blockDim.x){
        float x = (kk < Dd) ? src[kk] : 0.0f;
        __nv_bfloat16 h = __float2bfloat16(x);
        __nv_bfloat16 mm = __float2bfloat16(x - __bfloat162float(h));
        row[0*KSEG + kk] = h;   row[1*KSEG + kk] = mm;  row[2*KSEG + kk] = h;
    }
    if (threadIdx.x == 0) g_biasP[n] = bias[k];
}

// ---------------- 3. bf16 mma.sync GEMM (packed N, K=960) ----------------
__global__ __launch_bounds__(256, 1) void gemm_kernel(const int* __restrict__ doc_lens)
{
    __shared__ int s_pad;
    if (threadIdx.x == 0){
        int acc = 0;
        for (int i = 0; i < Bb; i++) acc += doc_lens[i];
        s_pad = (acc + TILE_M - 1) & ~(TILE_M - 1);
    }
    __syncthreads();
    const int blockM = blockIdx.y * TILE_M;
    if (blockM >= s_pad) return;

    extern __shared__ char smem[];
    const uint32_t sb = (uint32_t)__cvta_generic_to_shared(smem);
    const int tid = threadIdx.x;
    const int lane = tid & 31, wid = tid >> 5;
    const int wm = wid & 1, wn = wid >> 1;
    const int blockN = blockIdx.x * TILE_N;

    const __nv_bfloat16* gA = g_Aq + (size_t)blockM * KP;
    const __nv_bfloat16* gB = g_Bq + (size_t)blockN * KP;

    uint32_t t_soff[CPT];
    const __nv_bfloat16* t_gptr[CPT];
    #pragma unroll
    for (int q = 0; q < CPT; q++){
        int id = tid + q*256;
        int row = id >> 3, ch = id & 7;
        int isB = (row >= TILE_M);
        int r2  = isB ? (row - TILE_M) : row;
        t_soff[q] = (isB ? STAGE_A : 0) + r2*ROWB + ch*16;
        t_gptr[q] = (isB ? gB : gA) + (size_t)r2 * KP + ch*8;
    }

    const uint32_t aBase = sb + (wm*64 + (lane & 15)) * ROWB + (lane >> 4) * 16;
    const uint32_t bBase = sb + STAGE_A + (wn*64 + ((lane >> 4) << 3) + (lane & 7)) * ROWB
                              + (((lane >> 3) & 1) * 16);

    float acc[4][8][4];
    #pragma unroll
    for (int i = 0; i < 4; i++)
        #pragma unroll
        for (int j = 0; j < 8; j++)
            #pragma unroll
            for (int r = 0; r < 4; r++) acc[i][j][r] = 0.0f;

    #pragma unroll
    for (int s = 0; s < NSTG-1; s++){
        #pragma unroll
        for (int q = 0; q < CPT; q++)
            cpasync16(sb + s*STAGE_SZ + t_soff[q], t_gptr[q] + s*BK);
        cp_commit();
    }

    uint32_t a[2][4][4], b[2][8][2];

    for (int kt = 0; kt < NKT; kt++){
        cp_wait<NSTG-2>();
        __syncthreads();
        const uint32_t stage = (kt % NSTG) * STAGE_SZ;

        #pragma unroll
        for (int i = 0; i < 4; i++)
            ldsm4(aBase + stage + i*16*ROWB, a[0][i][0], a[0][i][1], a[0][i][2], a[0][i][3]);
        #pragma unroll
        for (int j2 = 0; j2 < 4; j2++){
            uint32_t r0, r1, r2, r3;
            ldsm4(bBase + stage + j2*16*ROWB, r0, r1, r2, r3);
            b[0][2*j2][0] = r0;   b[0][2*j2][1] = r1;
            b[0][2*j2+1][0] = r2; b[0][2*j2+1][1] = r3;
        }

        int nkt = kt + NSTG - 1;
        if (nkt < NKT){
            uint32_t stb = sb + (nkt % NSTG)*STAGE_SZ;
            #pragma unroll
            for (int q = 0; q < CPT; q++)
                cpasync16(stb + t_soff[q], t_gptr[q] + nkt*BK);
        }
        cp_commit();

        #pragma unroll
        for (int s = 0; s < 4; s++){
            const int cur = s & 1, nxt = cur ^ 1;
            if (s < 3){
                #pragma unroll
                for (int i = 0; i < 4; i++)
                    ldsm4(aBase + stage + i*16*ROWB + (s+1)*32,
                          a[nxt][i][0], a[nxt][i][1], a[nxt][i][2], a[nxt][i][3]);
                #pragma unroll
                for (int j2 = 0; j2 < 4; j2++){
                    uint32_t r0, r1, r2, r3;
                    ldsm4(bBase + stage + j2*16*ROWB + (s+1)*32, r0, r1, r2, r3);
                    b[nxt][2*j2][0] = r0;   b[nxt][2*j2][1] = r1;
                    b[nxt][2*j2+1][0] = r2; b[nxt][2*j2+1][1] = r3;
                }
            }
            #pragma unroll
            for (int i = 0; i < 4; i++)
                #pragma unroll
                for (int j = 0; j < 8; j++)
                    mma16816(acc[i][j], a[cur][i][0], a[cur][i][1], a[cur][i][2], a[cur][i][3],
                             b[cur][j][0], b[cur][j][1]);
        }
    }

    const int colBase = blockN + wn*64 + 2*(lane & 3);
    #pragma unroll
    for (int i = 0; i < 4; i++){
        int row0 = blockM + wm*64 + i*16 + (lane >> 2);
        float* r0p = g_ts + (size_t)row0 * NP + colBase;
        float* r1p = r0p + (size_t)8 * NP;
        #pragma unroll
        for (int j = 0; j < 8; j++){
            float2 bj = *(const float2*)(g_biasP + colBase + j*8);
            float2 v0 = make_float2(acc[i][j][0] + bj.x, acc[i][j][1] + bj.y);
            float2 v1 = make_float2(acc[i][j][2] + bj.x, acc[i][j][3] + bj.y);
            *(float2*)(r0p + j*8) = v0;
            *(float2*)(r1p + j*8) = v1;
        }
    }
}

// ---------------- 4. max-sum scan, packed columns, chunk-6 double buffer ----------------
template<int NST>
__device__ __forceinline__ void step_t(float* hid, float& sc, const float* f, const float* eps){
    float ae[NST];
    ae[0] = hid[0];
    #pragma unroll
    for (int m = 1; m < NST; m++) ae[m] = fmaxf(hid[m], hid[m-1] + eps[m-1]);
    float nh[NST];
    nh[0] = fmaxf(0.0f, ae[0] + f[0]);
    #pragma unroll
    for (int m = 1; m < NST; m++)
        nh[m] = fmaxf(ae[m-1] + f[NST + m - 1], ae[m] + f[m]);
    #pragma unroll
    for (int m = 0; m < NST; m++) hid[m] = nh[m];
    sc = fmaxf(sc, hid[NST-1]);
}

template<int NST>
__device__ __forceinline__ void load_t(float* buf, const float* base, int chunk){
    constexpr int W = 2*NST - 1;
    #pragma unroll
    for (int u = 0; u < SCH; u++){
        const float* q = base + (size_t)(chunk*SCH + u) * NP;
        #pragma unroll
        for (int j = 0; j < W; j++) buf[u*W + j] = q[j];
    }
}

template<int NST>
__device__ __forceinline__ void comp_t(float* hid, float& sc, const float* buf, const float* eps){
    constexpr int W = 2*NST - 1;
    #pragma unroll
    for (int u = 0; u < SCH; u++) step_t<NST>(hid, sc, buf + u*W, eps);
}

template<int NST>
__device__ __forceinline__ float scan_run(const float* base, int dl, const float* eps){
    constexpr int W = 2*NST - 1;
    float hid[NST];
    hid[0] = 0.0f;
    #pragma unroll
    for (int m = 1; m < NST; m++) hid[m] = NEGV;
    float sc = NEGV;
    const int nc = dl / SCH, rem = dl % SCH;

    float buf0[SCH*W], buf1[SCH*W];
    load_t<NST>(buf0, base, 0);

    int c = 0;
    #pragma unroll 1
    while (c + 2 <= nc){
        load_t<NST>(buf1, base, c + 1);
        comp_t<NST>(hid, sc, buf0, eps);
        if (c + 2 < nc) load_t<NST>(buf0, base, c + 2);
        comp_t<NST>(hid, sc, buf1, eps);
        c += 2;
    }
    if (c < nc) comp_t<NST>(hid, sc, buf0, eps);
    #pragma unroll 1
    for (int u = 0; u < rem; u++){
        const float* q = base + (size_t)(nc*SCH + u) * NP;
        float f[W];
        #pragma unroll
        for (int j = 0; j < W; j++) f[j] = q[j];
        step_t<NST>(hid, sc, f, eps);
    }
    return sc;
}

__global__ __launch_bounds__(64) void scan_kernel(const int* __restrict__ doc_lens,
                                                  const float* __restrict__ epsilons)
{
    int idx = blockIdx.x * 64 + threadIdx.x;
    int b = idx >> 9;
    int p = idx & 511;

    float eps[6];
    #pragma unroll
    for (int i = 0; i < 6; i++) eps[i] = epsilons[p*6 + i];
    const int dl = doc_lens[b];
    int off = 0;
    for (int i = 0; i < b; i++) off += doc_lens[i];

    float sc;
    if (p < 256){
        const float* base = g_ts + (size_t)off * NP + p*11;
        sc = scan_run<6>(base, dl, eps);
    } else {
        const float* base = g_ts + (size_t)off * NP + 2816 + (p - 256)*13;
        sc = scan_run<7>(base, dl, eps);
    }
    g_scores[idx] = sc;
}

// ---------------- 5. batchnorm + binarize + final linear ----------------
__global__ __launch_bounds__(512) void final_kernel(const float* __restrict__ bn_w,
                                                    const float* __restrict__ bn_b,
                                                    const float* __restrict__ fw,
                                                    const float* __restrict__ fb,
                                                    float* __restrict__ out)
{
    __shared__ unsigned char sbin[Bb][Pp];
    int p = threadIdx.x;

    float x[Bb];
    float s = 0.0f;
    #pragma unroll
    for (int b = 0; b < Bb; b++){ x[b] = g_scores[b*Pp + p]; s += x[b]; }
    float mean = s * (1.0f / Bb);
    float v = 0.0f;
    #pragma unroll
    for (int b = 0; b < Bb; b++){ float d = x[b] - mean; v += d * d; }
    v *= (1.0f / Bb);
    float inv = rsqrtf(v + 1e-5f);
    float w = bn_w[p], bb = bn_b[p];
    #pragma unroll
    for (int b = 0; b < Bb; b++){
        float y = (x[b] - mean) * inv * w + bb;
        sbin[b][p] = (y > 0.0f) ? 1 : 0;
    }
    __syncthreads();

    int warp = p >> 5, lane = p & 31;
    #pragma unroll
    for (int q = 0; q < 4; q++){
        int o = warp * 4 + q;
        int b = o >> 1, c = o & 1;
        float acc = 0.0f;
        for (int pp = lane; pp < Pp; pp += 32)
            if (sbin[b][pp]) acc += fw[c*Pp + pp];
        #pragma unroll
        for (int off = 16; off > 0; off >>= 1)
            acc += __shfl_xor_sync(0xffffffffu, acc, off);
        if (lane == 0) out[b*NCc + c] = acc + fb[c];
    }
}

// ---------------- host launch ----------------
extern "C" void kernel_launch(void* const* d_in, const int* in_sizes, int n_in,
                              void* d_out, int out_size)
{
    const int*   tokens    = (const int*)  d_in[0];
    const int*   doc_lens  = (const int*)  d_in[1];
    const float* emb_table = (const float*)d_in[2];
    const float* diags     = (const float*)d_in[3];
    const float* bias      = (const float*)d_in[4];
    const float* epsilons  = (const float*)d_in[5];
    const float* bn_weight = (const float*)d_in[6];
    const float* bn_bias   = (const float*)d_in[7];
    const float* final_w   = (const float*)d_in[8];
    const float* final_b   = (const float*)d_in[9];
    float* out = (float*)d_out;

    convA_kernel<<<Mm, 128>>>(tokens, emb_table, doc_lens);
    convB_kernel<<<NP, 128>>>(diags, bias);

    cudaFuncSetAttribute(gemm_kernel, cudaFuncAttributeMaxDynamicSharedMemorySize, SMEM_GEMM);
    dim3 grid(NP / TILE_N, Mm / TILE_M);   // (24, 32)
    gemm_kernel<<<grid, 256, SMEM_GEMM>>>(doc_lens);

    scan_kernel<<<(Bb*Pp) / 64, 64>>>(doc_lens, epsilons);
    final_kernel<<<1, 512>>>(bn_weight, bn_bias, final_w, final_b, out);
}